// round 3
// baseline (speedup 1.0000x reference)
#include <cuda_runtime.h>

#define NB    100   // neighbors
#define NF    13    // features
#define ROW4  (NB * NF / 4)      // 325 float4 per batch
#define WPB   4                  // warps per block
#define TPB   (WPB * 32)

__device__ __forceinline__ void jrot(float M[3][3], float V[3][3], int p, int q) {
    float apq = M[p][q];
    if (fabsf(apq) < 1e-20f) return;
    float theta = (M[q][q] - M[p][p]) * 0.5f / apq;
    float t = copysignf(1.0f, theta) / (fabsf(theta) + sqrtf(theta * theta + 1.0f));
    float c = rsqrtf(t * t + 1.0f);
    float s = t * c;
    float mpp = M[p][p], mqq = M[q][q];
    M[p][p] = mpp - t * apq;
    M[q][q] = mqq + t * apq;
    M[p][q] = 0.0f; M[q][p] = 0.0f;
    int r = 3 - p - q;
    float mrp = M[r][p], mrq = M[r][q];
    M[r][p] = c * mrp - s * mrq; M[p][r] = M[r][p];
    M[r][q] = s * mrp + c * mrq; M[q][r] = M[r][q];
#pragma unroll
    for (int i = 0; i < 3; i++) {
        float vip = V[i][p], viq = V[i][q];
        V[i][p] = c * vip - s * viq;
        V[i][q] = s * vip + c * viq;
    }
}

__global__ void __launch_bounds__(TPB) svd_align_kernel(
    const float* __restrict__ in,
    const float* __restrict__ pa,
    const float* __restrict__ pb,
    const float* __restrict__ pshift,
    float* __restrict__ out,
    int B)
{
    __shared__ float sdat[WPB][NB * NF];

    const int wid  = threadIdx.x >> 5;
    const int lane = threadIdx.x & 31;
    const int wb   = blockIdx.x * WPB + wid;   // batch handled by this warp
    if (wb >= B) return;

    const float a     = pa[0];
    const float bbias = pb[0];
    const float shift = pshift[0];

    float* sm = sdat[wid];

    // ---- stage batch row into SMEM: 325 float4, coalesced ----
    const float4* src = (const float4*)(in + (size_t)wb * (NB * NF));
    float4* dst = (float4*)sm;
#pragma unroll
    for (int i = 0; i < 11; i++) {
        int q = i * 32 + lane;
        if (q < ROW4) dst[q] = src[q];
    }
    __syncwarp();

    // ---- partials over 100 neighbors, 3-4 rows per lane ----
    // [w, w*v1(3), w*v2(3), w*v2_k*v1_j(9)]
    float acc[16];
#pragma unroll
    for (int k = 0; k < 16; k++) acc[k] = 0.0f;

#pragma unroll
    for (int c = 0; c < 4; c++) {
        int n = c * 32 + lane;
        if (n < NB) {
            const float* r = &sm[n * NF];
            float w = a * r[0] + bbias;
            w = (w > 0.0f ? w : 0.0f) + 1e-8f;
            float v1[3], v2[3], wv2[3];
#pragma unroll
            for (int k = 0; k < 3; k++) {
                v1[k] = fmaf(shift, r[7 + k],  r[1 + k]);
                v2[k] = fmaf(shift, r[10 + k], r[4 + k]);
            }
            acc[0] += w;
#pragma unroll
            for (int k = 0; k < 3; k++) {
                acc[1 + k] = fmaf(w, v1[k], acc[1 + k]);
                wv2[k]     = w * v2[k];
                acc[4 + k] += wv2[k];
            }
#pragma unroll
            for (int k = 0; k < 3; k++)
#pragma unroll
                for (int j = 0; j < 3; j++)
                    acc[7 + k * 3 + j] = fmaf(wv2[k], v1[j], acc[7 + k * 3 + j]);
        }
    }

    // ---- warp-only shuffle reduce (to lane 0) ----
#pragma unroll
    for (int k = 0; k < 16; k++) {
#pragma unroll
        for (int off = 16; off > 0; off >>= 1)
            acc[k] += __shfl_down_sync(0xffffffffu, acc[k], off);
    }

    // ---- lane 0: 3x3 weighted-Kabsch SVD ----
    float R00, R01, R02, R10, R11, R12, R20, R21, R22, t0, t1, t2;
    if (lane == 0) {
        const float inv_w = 1.0f / acc[0];
        float v1c[3], v2c[3];
#pragma unroll
        for (int k = 0; k < 3; k++) { v1c[k] = acc[1 + k] * inv_w; v2c[k] = acc[4 + k] * inv_w; }

        float A[3][3];
#pragma unroll
        for (int k = 0; k < 3; k++)
#pragma unroll
            for (int j = 0; j < 3; j++)
                A[k][j] = acc[7 + k * 3 + j] - acc[4 + k] * acc[1 + j] * inv_w;

        float M[3][3];
#pragma unroll
        for (int i = 0; i < 3; i++)
#pragma unroll
            for (int j = 0; j < 3; j++) {
                float s = 0.0f;
#pragma unroll
                for (int k = 0; k < 3; k++) s += A[k][i] * A[k][j];
                M[i][j] = s;
            }

        float V[3][3] = {{1,0,0},{0,1,0},{0,0,1}};
#pragma unroll
        for (int sweep = 0; sweep < 5; sweep++) {
            jrot(M, V, 0, 1);
            jrot(M, V, 0, 2);
            jrot(M, V, 1, 2);
        }

        // sort eigenvalues descending (det correction lands on smallest dir)
        float e[3] = { M[0][0], M[1][1], M[2][2] };
#pragma unroll
        for (int i = 0; i < 2; i++)
#pragma unroll
            for (int j = 0; j < 2 - i; j++) {
                if (e[j] < e[j + 1]) {
                    float te = e[j]; e[j] = e[j + 1]; e[j + 1] = te;
#pragma unroll
                    for (int r = 0; r < 3; r++) {
                        float tv = V[r][j]; V[r][j] = V[r][j + 1]; V[r][j + 1] = tv;
                    }
                }
            }

        float U[3][3];
#pragma unroll
        for (int k = 0; k < 2; k++)
#pragma unroll
            for (int i = 0; i < 3; i++)
                U[i][k] = A[i][0] * V[0][k] + A[i][1] * V[1][k] + A[i][2] * V[2][k];

        float n0 = rsqrtf(U[0][0]*U[0][0] + U[1][0]*U[1][0] + U[2][0]*U[2][0] + 1e-30f);
#pragma unroll
        for (int i = 0; i < 3; i++) U[i][0] *= n0;
        float d01 = U[0][0]*U[0][1] + U[1][0]*U[1][1] + U[2][0]*U[2][1];
#pragma unroll
        for (int i = 0; i < 3; i++) U[i][1] -= d01 * U[i][0];
        float n1 = rsqrtf(U[0][1]*U[0][1] + U[1][1]*U[1][1] + U[2][1]*U[2][1] + 1e-30f);
#pragma unroll
        for (int i = 0; i < 3; i++) U[i][1] *= n1;
        U[0][2] = U[1][0]*U[2][1] - U[2][0]*U[1][1];
        U[1][2] = U[2][0]*U[0][1] - U[0][0]*U[2][1];
        U[2][2] = U[0][0]*U[1][1] - U[1][0]*U[0][1];

        float detV =
            V[0][0] * (V[1][1]*V[2][2] - V[2][1]*V[1][2]) -
            V[0][1] * (V[1][0]*V[2][2] - V[2][0]*V[1][2]) +
            V[0][2] * (V[1][0]*V[2][1] - V[2][0]*V[1][1]);
        float d3 = (detV > 0.0f) ? 1.0f : -1.0f;

        float R[3][3];
#pragma unroll
        for (int i = 0; i < 3; i++)
#pragma unroll
            for (int j = 0; j < 3; j++)
                R[i][j] = V[i][0]*U[j][0] + V[i][1]*U[j][1] + d3 * V[i][2]*U[j][2];

        R00 = R[0][0]; R01 = R[0][1]; R02 = R[0][2];
        R10 = R[1][0]; R11 = R[1][1]; R12 = R[1][2];
        R20 = R[2][0]; R21 = R[2][1]; R22 = R[2][2];
        t0 = v1c[0] - (R[0][0]*v2c[0] + R[0][1]*v2c[1] + R[0][2]*v2c[2]);
        t1 = v1c[1] - (R[1][0]*v2c[0] + R[1][1]*v2c[1] + R[1][2]*v2c[2]);
        t2 = v1c[2] - (R[2][0]*v2c[0] + R[2][1]*v2c[1] + R[2][2]*v2c[2]);
    }

    // broadcast R, t to all lanes
    float Rt[12];
    Rt[0]=R00; Rt[1]=R01; Rt[2]=R02; Rt[3]=R10; Rt[4]=R11; Rt[5]=R12;
    Rt[6]=R20; Rt[7]=R21; Rt[8]=R22; Rt[9]=t0; Rt[10]=t1; Rt[11]=t2;
#pragma unroll
    for (int k = 0; k < 12; k++) Rt[k] = __shfl_sync(0xffffffffu, Rt[k], 0);

    // ---- apply: 600 outputs as 150 float4, coalesced STG.128 ----
    float* ob = out + (size_t)wb * (NB * 6);
#pragma unroll
    for (int it = 0; it < 5; it++) {
        int q = it * 32 + lane;          // float4 index, < 150
        if (q < 150) {
            float4 o;
            float* op = (float*)&o;
#pragma unroll
            for (int s = 0; s < 4; s++) {
                int e = q * 4 + s;       // output element index < 600
                int n = e / 6;
                int c = e - n * 6;
                int ci  = (c < 3) ? c : c - 3;
                int off = (c < 3) ? 4 : 10;
                const float* row = &sm[n * NF];
                float val = Rt[ci*3 + 0] * row[off + 0]
                          + Rt[ci*3 + 1] * row[off + 1]
                          + Rt[ci*3 + 2] * row[off + 2];
                if (c < 3) val += Rt[9 + ci];
                op[s] = val;
            }
            ((float4*)ob)[q] = o;
        }
    }
}

extern "C" void kernel_launch(void* const* d_in, const int* in_sizes, int n_in,
                              void* d_out, int out_size) {
    const float* net   = (const float*)d_in[0];
    const float* a     = (const float*)d_in[1];
    const float* b     = (const float*)d_in[2];
    const float* shift = (const float*)d_in[3];
    float* out = (float*)d_out;

    int B = in_sizes[0] / (NB * NF);   // 100000
    int grid = (B + WPB - 1) / WPB;
    svd_align_kernel<<<grid, TPB>>>(net, a, b, shift, out, B);
}

// round 4
// speedup vs baseline: 2.7294x; 2.7294x over previous
#include <cuda_runtime.h>

#define NB    100   // neighbors
#define NF    13    // features
#define ROW4  (NB * NF / 4)      // 325 float4 per batch
#define WPB   4                  // warps per block
#define TPB   (WPB * 32)

// Branch-free, fast-division Jacobi rotation on symmetric M, accumulating V.
// t = apq / copysign(|D| + sqrt(D^2 + apq^2), D),  D = (Mqq - Mpp)/2.
// apq==0 -> t==0 -> identity rotation (no special-casing needed).
__device__ __forceinline__ void jrot(float M[3][3], float V[3][3], int p, int q) {
    float apq = M[p][q];
    float D   = 0.5f * (M[q][q] - M[p][p]);
    float hyp = sqrtf(fmaf(D, D, fmaf(apq, apq, 1e-38f)));
    float t   = __fdividef(apq, copysignf(fabsf(D) + hyp, D));
    float c   = rsqrtf(fmaf(t, t, 1.0f));
    float s   = t * c;
    float tapq = t * apq;
    M[p][p] -= tapq;
    M[q][q] += tapq;
    M[p][q] = 0.0f; M[q][p] = 0.0f;
    const int r = 3 - p - q;
    float mrp = M[r][p], mrq = M[r][q];
    M[r][p] = fmaf(c, mrp, -s * mrq); M[p][r] = M[r][p];
    M[r][q] = fmaf(s, mrp,  c * mrq); M[q][r] = M[r][q];
#pragma unroll
    for (int i = 0; i < 3; i++) {
        float vip = V[i][p], viq = V[i][q];
        V[i][p] = fmaf(c, vip, -s * viq);
        V[i][q] = fmaf(s, vip,  c * viq);
    }
}

__global__ void __launch_bounds__(TPB) svd_align_kernel(
    const float* __restrict__ in,
    const float* __restrict__ pa,
    const float* __restrict__ pb,
    const float* __restrict__ pshift,
    float* __restrict__ out,
    int B)
{
    __shared__ float sdat[WPB][NB * NF];

    const int wid  = threadIdx.x >> 5;
    const int lane = threadIdx.x & 31;
    const int wb   = blockIdx.x * WPB + wid;
    if (wb >= B) return;

    const float a     = pa[0];
    const float bbias = pb[0];
    const float shift = pshift[0];

    float* sm = sdat[wid];

    // ---- stage batch row into SMEM: 325 float4, coalesced ----
    const float4* src = (const float4*)(in + (size_t)wb * (NB * NF));
    float4* dst = (float4*)sm;
#pragma unroll
    for (int i = 0; i < 11; i++) {
        int q = i * 32 + lane;
        if (q < ROW4) dst[q] = src[q];
    }
    __syncwarp();

    // ---- partials: [w, w*v1(3), w*v2(3), w*v2_k*v1_j(9)] ----
    float acc[16];
#pragma unroll
    for (int k = 0; k < 16; k++) acc[k] = 0.0f;

#pragma unroll
    for (int c = 0; c < 4; c++) {
        int n = c * 32 + lane;
        if (c < 3 || lane < NB - 96) {
            const float* r = &sm[n * NF];
            float w = fmaf(a, r[0], bbias);
            w = fmaxf(w, 0.0f) + 1e-8f;
            float v1[3], v2[3], wv2[3];
#pragma unroll
            for (int k = 0; k < 3; k++) {
                v1[k] = fmaf(shift, r[7 + k],  r[1 + k]);
                v2[k] = fmaf(shift, r[10 + k], r[4 + k]);
            }
            acc[0] += w;
#pragma unroll
            for (int k = 0; k < 3; k++) {
                acc[1 + k] = fmaf(w, v1[k], acc[1 + k]);
                wv2[k]     = w * v2[k];
                acc[4 + k] += wv2[k];
            }
#pragma unroll
            for (int k = 0; k < 3; k++)
#pragma unroll
                for (int j = 0; j < 3; j++)
                    acc[7 + k * 3 + j] = fmaf(wv2[k], v1[j], acc[7 + k * 3 + j]);
        }
    }

    // ---- register-exchange butterfly reduce: 16 vals x 32 lanes ----
    // After each step, each lane keeps half the value-set; lane bit b selects
    // which half. Final per-lane value k(l) = 8*b0 + 4*b1 + 2*b2 + b3.
    float r8[8];
#pragma unroll
    for (int k = 0; k < 8; k++) {
        float snd = (lane & 1) ? acc[k] : acc[k + 8];
        float rcv = __shfl_xor_sync(0xffffffffu, snd, 1);
        float kep = (lane & 1) ? acc[k + 8] : acc[k];
        r8[k] = kep + rcv;
    }
    float r4[4];
#pragma unroll
    for (int k = 0; k < 4; k++) {
        float snd = (lane & 2) ? r8[k] : r8[k + 4];
        float rcv = __shfl_xor_sync(0xffffffffu, snd, 2);
        float kep = (lane & 2) ? r8[k + 4] : r8[k];
        r4[k] = kep + rcv;
    }
    float r2[2];
#pragma unroll
    for (int k = 0; k < 2; k++) {
        float snd = (lane & 4) ? r4[k] : r4[k + 2];
        float rcv = __shfl_xor_sync(0xffffffffu, snd, 4);
        float kep = (lane & 4) ? r4[k + 2] : r4[k];
        r2[k] = kep + rcv;
    }
    float snd1 = (lane & 8) ? r2[0] : r2[1];
    float rcv1 = __shfl_xor_sync(0xffffffffu, snd1, 8);
    float kep1 = (lane & 8) ? r2[1] : r2[0];
    float red  = kep1 + rcv1;
    red += __shfl_xor_sync(0xffffffffu, red, 16);

    // gather all 16 sums to every lane's f[] (lane0 uses them); src = 4-bit bit-reversal
    float f[16];
    f[0]  = __shfl_sync(0xffffffffu, red, 0);
    f[1]  = __shfl_sync(0xffffffffu, red, 8);
    f[2]  = __shfl_sync(0xffffffffu, red, 4);
    f[3]  = __shfl_sync(0xffffffffu, red, 12);
    f[4]  = __shfl_sync(0xffffffffu, red, 2);
    f[5]  = __shfl_sync(0xffffffffu, red, 10);
    f[6]  = __shfl_sync(0xffffffffu, red, 6);
    f[7]  = __shfl_sync(0xffffffffu, red, 14);
    f[8]  = __shfl_sync(0xffffffffu, red, 1);
    f[9]  = __shfl_sync(0xffffffffu, red, 9);
    f[10] = __shfl_sync(0xffffffffu, red, 5);
    f[11] = __shfl_sync(0xffffffffu, red, 13);
    f[12] = __shfl_sync(0xffffffffu, red, 3);
    f[13] = __shfl_sync(0xffffffffu, red, 11);
    f[14] = __shfl_sync(0xffffffffu, red, 7);
    f[15] = __shfl_sync(0xffffffffu, red, 15);

    // ---- lane 0: 3x3 weighted-Kabsch SVD ----
    float R00=0, R01=0, R02=0, R10=0, R11=0, R12=0, R20=0, R21=0, R22=0, t0=0, t1=0, t2=0;
    if (lane == 0) {
        const float inv_w = __fdividef(1.0f, f[0]);
        float v1c[3], v2c[3];
#pragma unroll
        for (int k = 0; k < 3; k++) { v1c[k] = f[1 + k] * inv_w; v2c[k] = f[4 + k] * inv_w; }

        float A[3][3];
#pragma unroll
        for (int k = 0; k < 3; k++)
#pragma unroll
            for (int j = 0; j < 3; j++)
                A[k][j] = fmaf(-f[4 + k] * inv_w, f[1 + j], f[7 + k * 3 + j]);

        float M[3][3];
#pragma unroll
        for (int i = 0; i < 3; i++)
#pragma unroll
            for (int j = 0; j < 3; j++) {
                float s = A[0][i] * A[0][j];
                s = fmaf(A[1][i], A[1][j], s);
                s = fmaf(A[2][i], A[2][j], s);
                M[i][j] = s;
            }

        float V[3][3] = {{1,0,0},{0,1,0},{0,0,1}};
#pragma unroll
        for (int sweep = 0; sweep < 4; sweep++) {
            jrot(M, V, 0, 1);
            jrot(M, V, 0, 2);
            jrot(M, V, 1, 2);
        }

        // branch-free sort: eigenvalues descending (3 compare-swaps via FSEL)
        float e0 = M[0][0], e1 = M[1][1], e2 = M[2][2];
        float c0[3] = { V[0][0], V[1][0], V[2][0] };
        float c1[3] = { V[0][1], V[1][1], V[2][1] };
        float c2[3] = { V[0][2], V[1][2], V[2][2] };
        {
            bool sw = e0 < e1;
            float te = sw ? e1 : e0; e1 = sw ? e0 : e1; e0 = te;
#pragma unroll
            for (int i = 0; i < 3; i++) { float tv = sw ? c1[i] : c0[i]; c1[i] = sw ? c0[i] : c1[i]; c0[i] = tv; }
        }
        {
            bool sw = e1 < e2;
            float te = sw ? e2 : e1; e2 = sw ? e1 : e2; e1 = te;
#pragma unroll
            for (int i = 0; i < 3; i++) { float tv = sw ? c2[i] : c1[i]; c2[i] = sw ? c1[i] : c2[i]; c1[i] = tv; }
        }
        {
            bool sw = e0 < e1;
            float te = sw ? e1 : e0; e1 = sw ? e0 : e1; e0 = te;
#pragma unroll
            for (int i = 0; i < 3; i++) { float tv = sw ? c1[i] : c0[i]; c1[i] = sw ? c0[i] : c1[i]; c0[i] = tv; }
        }

        // U columns: u0 = norm(A c0); u1 = orth-norm(A c1); u2 = u0 x u1
        float u0[3], u1[3], u2[3];
#pragma unroll
        for (int i = 0; i < 3; i++) {
            u0[i] = A[i][0] * c0[0] + A[i][1] * c0[1] + A[i][2] * c0[2];
            u1[i] = A[i][0] * c1[0] + A[i][1] * c1[1] + A[i][2] * c1[2];
        }
        float n0 = rsqrtf(fmaf(u0[0], u0[0], fmaf(u0[1], u0[1], fmaf(u0[2], u0[2], 1e-30f))));
#pragma unroll
        for (int i = 0; i < 3; i++) u0[i] *= n0;
        float d01 = u0[0]*u1[0] + u0[1]*u1[1] + u0[2]*u1[2];
#pragma unroll
        for (int i = 0; i < 3; i++) u1[i] = fmaf(-d01, u0[i], u1[i]);
        float n1 = rsqrtf(fmaf(u1[0], u1[0], fmaf(u1[1], u1[1], fmaf(u1[2], u1[2], 1e-30f))));
#pragma unroll
        for (int i = 0; i < 3; i++) u1[i] *= n1;
        u2[0] = u0[1]*u1[2] - u0[2]*u1[1];
        u2[1] = u0[2]*u1[0] - u0[0]*u1[2];
        u2[2] = u0[0]*u1[1] - u0[1]*u1[0];

        // det(U)=+1 by construction; d3 = sign(det V)
        float detV =
            c0[0] * (c1[1]*c2[2] - c1[2]*c2[1]) -
            c1[0] * (c0[1]*c2[2] - c0[2]*c2[1]) +
            c2[0] * (c0[1]*c1[2] - c0[2]*c1[1]);
        float d3 = (detV > 0.0f) ? 1.0f : -1.0f;

        // R = c0 u0^T + c1 u1^T + d3 c2 u2^T
        float c2d[3] = { d3 * c2[0], d3 * c2[1], d3 * c2[2] };
        R00 = c0[0]*u0[0] + c1[0]*u1[0] + c2d[0]*u2[0];
        R01 = c0[0]*u0[1] + c1[0]*u1[1] + c2d[0]*u2[1];
        R02 = c0[0]*u0[2] + c1[0]*u1[2] + c2d[0]*u2[2];
        R10 = c0[1]*u0[0] + c1[1]*u1[0] + c2d[1]*u2[0];
        R11 = c0[1]*u0[1] + c1[1]*u1[1] + c2d[1]*u2[1];
        R12 = c0[1]*u0[2] + c1[1]*u1[2] + c2d[1]*u2[2];
        R20 = c0[2]*u0[0] + c1[2]*u1[0] + c2d[2]*u2[0];
        R21 = c0[2]*u0[1] + c1[2]*u1[1] + c2d[2]*u2[1];
        R22 = c0[2]*u0[2] + c1[2]*u1[2] + c2d[2]*u2[2];
        t0 = v1c[0] - (R00*v2c[0] + R01*v2c[1] + R02*v2c[2]);
        t1 = v1c[1] - (R10*v2c[0] + R11*v2c[1] + R12*v2c[2]);
        t2 = v1c[2] - (R20*v2c[0] + R21*v2c[1] + R22*v2c[2]);
    }

    // broadcast R, t
    float Rt[12];
    Rt[0]=R00; Rt[1]=R01; Rt[2]=R02; Rt[3]=R10; Rt[4]=R11; Rt[5]=R12;
    Rt[6]=R20; Rt[7]=R21; Rt[8]=R22; Rt[9]=t0; Rt[10]=t1; Rt[11]=t2;
#pragma unroll
    for (int k = 0; k < 12; k++) Rt[k] = __shfl_sync(0xffffffffu, Rt[k], 0);

    // ---- apply: one neighbor per lane, 3x STG.64 (8B-aligned), no index math ----
    float* ob = out + (size_t)wb * (NB * 6);
#pragma unroll
    for (int c = 0; c < 4; c++) {
        int n = c * 32 + lane;
        if (c < 3 || lane < NB - 96) {
            const float* row = &sm[n * NF];
            float x0 = row[4],  x1 = row[5],  x2 = row[6];
            float m0 = row[10], m1 = row[11], m2 = row[12];
            float2 o0, o1, o2;
            o0.x = fmaf(Rt[0], x0, fmaf(Rt[1], x1, fmaf(Rt[2], x2, Rt[9])));
            o0.y = fmaf(Rt[3], x0, fmaf(Rt[4], x1, fmaf(Rt[5], x2, Rt[10])));
            o1.x = fmaf(Rt[6], x0, fmaf(Rt[7], x1, fmaf(Rt[8], x2, Rt[11])));
            o1.y = fmaf(Rt[0], m0, fmaf(Rt[1], m1, Rt[2] * m2));
            o2.x = fmaf(Rt[3], m0, fmaf(Rt[4], m1, Rt[5] * m2));
            o2.y = fmaf(Rt[6], m0, fmaf(Rt[7], m1, Rt[8] * m2));
            float2* op = (float2*)(ob + n * 6);
            op[0] = o0; op[1] = o1; op[2] = o2;
        }
    }
}

extern "C" void kernel_launch(void* const* d_in, const int* in_sizes, int n_in,
                              void* d_out, int out_size) {
    const float* net   = (const float*)d_in[0];
    const float* a     = (const float*)d_in[1];
    const float* b     = (const float*)d_in[2];
    const float* shift = (const float*)d_in[3];
    float* out = (float*)d_out;

    int B = in_sizes[0] / (NB * NF);   // 100000
    int grid = (B + WPB - 1) / WPB;
    svd_align_kernel<<<grid, TPB>>>(net, a, b, shift, out, B);
}